// round 7
// baseline (speedup 1.0000x reference)
#include <cuda_runtime.h>
#include <cuda.h>
#include <cuda_fp16.h>
#include <math.h>
#include <stdint.h>

#define NB 8
#define SS 2048
#define HH 1024
#define MM 1024
#define MP 1026   // padded rows per batch (zero row below m=0 and above m=1023)

#define C_H0 0.48296291314469025f
#define C_H1 0.83651630373780790f
#define C_H2 0.22414386804185735f
#define C_H3 (-0.12940952255092145f)

// GEMM tiling: CTA 128x128, BK=64, 3-stage TMA pipeline, SW128
// 4 warps (128 threads), warp tile 64x64 (2x2 warp grid)
#define BK 64
#define TILEB 16384           // 128 rows x 128B per operand tile
#define STAGEB (2 * TILEB)    // A + B
#define SMEM_BYTES (3 * STAGEB + 64)

// ---------------- device scratch ----------------
__device__ __align__(16) __half g_ca[NB * MP * HH];
__device__ __align__(16) __half g_cd[NB * MP * HH];
__device__ __align__(16) __half g_pa[NB * MM * HH];
__device__ __align__(16) __half g_pd[NB * MM * HH];
__device__ __align__(16) __half g_rec[NB * SS * HH];
__device__ __align__(16) __half g_wc[2 * HH * 3072];  // [which][o][delta*1024+h]
__device__ __align__(16) __half g_wo[HH * HH];        // [o][h]

// ---------------- helpers ----------------
__device__ __forceinline__ uint32_t smem_u32(const void* p) {
    uint32_t a;
    asm("{ .reg .u64 t; cvta.to.shared.u64 t, %1; cvt.u32.u64 %0, t; }" : "=r"(a) : "l"(p));
    return a;
}

__device__ __forceinline__ uint32_t sw128(uint32_t o) {  // SW128: bits[6:4] ^= bits[9:7]
    return o ^ ((o >> 3) & 0x70);
}

__device__ __forceinline__ void ldm_x4(uint32_t& r0, uint32_t& r1, uint32_t& r2, uint32_t& r3,
                                       uint32_t addr) {
    asm volatile("ldmatrix.sync.aligned.m8n8.x4.shared.b16 {%0,%1,%2,%3}, [%4];"
                 : "=r"(r0), "=r"(r1), "=r"(r2), "=r"(r3) : "r"(addr));
}

__device__ __forceinline__ void mma16816(float* d, const uint32_t* a, const uint32_t* b) {
    asm volatile(
        "mma.sync.aligned.m16n8k16.row.col.f32.f16.f16.f32 "
        "{%0,%1,%2,%3}, {%4,%5,%6,%7}, {%8,%9}, {%0,%1,%2,%3};"
        : "+f"(d[0]), "+f"(d[1]), "+f"(d[2]), "+f"(d[3])
        : "r"(a[0]), "r"(a[1]), "r"(a[2]), "r"(a[3]), "r"(b[0]), "r"(b[1]));
}

__device__ __forceinline__ void tma2d(uint32_t dst, const CUtensorMap* tm, int x, int y,
                                      uint32_t mb) {
    asm volatile(
        "cp.async.bulk.tensor.2d.shared::cta.global.tile.mbarrier::complete_tx::bytes "
        "[%0], [%1, {%2, %3}], [%4];"
        :: "r"(dst), "l"(tm), "r"(x), "r"(y), "r"(mb) : "memory");
}

__device__ __forceinline__ void mbar_init(uint32_t mb, uint32_t cnt) {
    asm volatile("mbarrier.init.shared.b64 [%0], %1;" :: "r"(mb), "r"(cnt) : "memory");
}

__device__ __forceinline__ void mbar_expect(uint32_t mb, uint32_t bytes) {
    asm volatile("mbarrier.arrive.expect_tx.shared.b64 _, [%0], %1;"
                 :: "r"(mb), "r"(bytes) : "memory");
}

__device__ __forceinline__ void mbar_wait(uint32_t mb, uint32_t parity) {
    asm volatile(
        "{\n\t.reg .pred P;\n\t"
        "LAB_%=:\n\t"
        "mbarrier.try_wait.parity.acquire.cta.shared::cta.b64 P, [%0], %1, 0x989680;\n\t"
        "@!P bra LAB_%=;\n\t"
        "}" :: "r"(mb), "r"(parity) : "memory");
}

__device__ __forceinline__ float gelu_exact(float v) {
    return 0.5f * v * (1.0f + erff(v * 0.70710678118654752f));
}

// ---------------- weight prep ----------------
__global__ void prep_conv_w(const float* __restrict__ wA, const float* __restrict__ wD) {
    int idx = blockIdx.x * 256 + threadIdx.x;   // 0 .. 2*1024*1024-1
    int which = idx >> 20;
    int oh = idx & ((1 << 20) - 1);
    int o = oh >> 10, h = oh & 1023;
    const float* w = which ? wD : wA;
    __half* W = g_wc + (size_t)which * HH * 3072;
    const float* p = w + ((size_t)o * HH + h) * 3;
#pragma unroll
    for (int d = 0; d < 3; d++)
        W[(size_t)o * 3072 + d * 1024 + h] = __float2half_rn(p[d]);
}

__global__ void prep_out_w(const float* __restrict__ w) {
    int idx = blockIdx.x * 256 + threadIdx.x;  // 0..1M-1
    g_wo[idx] = __float2half_rn(w[idx]);
}

// zero padding rows (padrow 0 and 1025 of each batch)
__global__ void zero_pad_kernel() {
    int b = blockIdx.x >> 1;
    int top = blockIdx.x & 1;
    size_t off = ((size_t)b * MP + (top ? 1025 : 0)) * HH + threadIdx.x * 4;
    uint2 z = make_uint2(0u, 0u);
    *(uint2*)(g_ca + off) = z;
    *(uint2*)(g_cd + off) = z;
}

// ---------------- DWT -> fp16 (padded rows) ----------------
__global__ void dwt_kernel(const float* __restrict__ x) {
    int bm = blockIdx.x;
    int b = bm >> 10, m = bm & 1023;
    int h = threadIdx.x << 2;
    int s0 = 2 * m - 2, s1 = 2 * m - 1;
    if (s0 < 0) s0 = -s0 - 1;
    if (s1 < 0) s1 = -s1 - 1;
    const float* xb = x + (size_t)b * SS * HH + h;
    float4 v0 = *(const float4*)(xb + (size_t)s0 * HH);
    float4 v1 = *(const float4*)(xb + (size_t)s1 * HH);
    float4 v2 = *(const float4*)(xb + (size_t)(2 * m) * HH);
    float4 v3 = *(const float4*)(xb + (size_t)(2 * m + 1) * HH);
    __half ca[4], cd[4];
    ca[0] = __float2half_rn(C_H0 * v0.x + C_H1 * v1.x + C_H2 * v2.x + C_H3 * v3.x);
    ca[1] = __float2half_rn(C_H0 * v0.y + C_H1 * v1.y + C_H2 * v2.y + C_H3 * v3.y);
    ca[2] = __float2half_rn(C_H0 * v0.z + C_H1 * v1.z + C_H2 * v2.z + C_H3 * v3.z);
    ca[3] = __float2half_rn(C_H0 * v0.w + C_H1 * v1.w + C_H2 * v2.w + C_H3 * v3.w);
    cd[0] = __float2half_rn(C_H3 * v0.x - C_H2 * v1.x + C_H1 * v2.x - C_H0 * v3.x);
    cd[1] = __float2half_rn(C_H3 * v0.y - C_H2 * v1.y + C_H1 * v2.y - C_H0 * v3.y);
    cd[2] = __float2half_rn(C_H3 * v0.z - C_H2 * v1.z + C_H1 * v2.z - C_H0 * v3.z);
    cd[3] = __float2half_rn(C_H3 * v0.w - C_H2 * v1.w + C_H1 * v2.w - C_H0 * v3.w);
    size_t off = ((size_t)b * MP + m + 1) * HH + h;
    *(uint2*)(g_ca + off) = *(const uint2*)ca;
    *(uint2*)(g_cd + off) = *(const uint2*)cd;
}

// ---------------- iDWT: fp16 pa/pd -> fp16 recon ----------------
__global__ void idwt_kernel() {
    int bn = blockIdx.x;
    int b = bn >> 11, n = bn & 2047;
    int h = threadIdx.x << 2;
    size_t outoff = ((size_t)b * SS + n) * HH + h;
    if (n >= 2046) {
        *(uint2*)(g_rec + outoff) = make_uint2(0u, 0u);
        return;
    }
    int m0, m1;
    float wa0, wa1, wd0, wd1;
    if (!(n & 1)) {
        m0 = n >> 1; m1 = m0 + 1;
        wa1 = C_H0; wa0 = C_H2; wd1 = C_H3; wd0 = C_H1;
    } else {
        m0 = (n - 1) >> 1; m1 = m0 + 1;
        wa1 = C_H1; wa0 = C_H3; wd1 = -C_H2; wd0 = -C_H0;
    }
    size_t base = (size_t)b * MM * HH + h;
    uint2 ua0 = *(const uint2*)(g_pa + base + (size_t)m0 * HH);
    uint2 ua1 = *(const uint2*)(g_pa + base + (size_t)m1 * HH);
    uint2 ud0 = *(const uint2*)(g_pd + base + (size_t)m0 * HH);
    uint2 ud1 = *(const uint2*)(g_pd + base + (size_t)m1 * HH);
    const __half2* a0 = (const __half2*)&ua0;
    const __half2* a1 = (const __half2*)&ua1;
    const __half2* d0 = (const __half2*)&ud0;
    const __half2* d1 = (const __half2*)&ud1;
    __half rv[4];
#pragma unroll
    for (int q = 0; q < 2; q++) {
        float2 fa0 = __half22float2(a0[q]);
        float2 fa1 = __half22float2(a1[q]);
        float2 fd0 = __half22float2(d0[q]);
        float2 fd1 = __half22float2(d1[q]);
        rv[2 * q + 0] = __float2half_rn(wa0 * fa0.x + wa1 * fa1.x + wd0 * fd0.x + wd1 * fd1.x);
        rv[2 * q + 1] = __float2half_rn(wa0 * fa0.y + wa1 * fa1.y + wd0 * fd0.y + wd1 * fd1.y);
    }
    *(uint2*)(g_rec + outoff) = *(const uint2*)rv;
}

// ---------------------------------------------------------------------------
// fp16 GEMM body, TMA-fed: C[M,1024] = A[M,K] * B[1024,K]^T (+bias, opt GELU)
// 128 threads, 2x2 warp grid, warp tile 64x64. 3 stages, BK=64, SW128.
// ---------------------------------------------------------------------------
template <bool CONV, bool GELU, typename OT>
__device__ __forceinline__ void gemm_body(
    const CUtensorMap* __restrict__ tmA, const CUtensorMap* __restrict__ tmB,
    const float* __restrict__ bias, OT* __restrict__ C,
    int kChunks, char* smem) {

    const uint32_t sbase = smem_u32(smem);
    const uint32_t mbars = sbase + 3 * STAGEB;

    const int tid = threadIdx.x;
    const int lane = tid & 31;
    const int wid = tid >> 5;
    const int row0 = blockIdx.y << 7;
    const int col0 = blockIdx.x << 7;
    const int arowBase = CONV ? ((row0 >> 10) * MP + (row0 & 1023)) : row0;

    if (tid == 0) {
        mbar_init(mbars + 0, 1);
        mbar_init(mbars + 8, 1);
        mbar_init(mbars + 16, 1);
    }
    __syncthreads();

    // prologue: stages 0,1
    if (tid == 0) {
#pragma unroll
        for (int c = 0; c < 2; c++) {
            const int k0 = c * BK;
            const uint32_t mb = mbars + c * 8;
            mbar_expect(mb, 2 * TILEB);
            const int ax = CONV ? (k0 & 1023) : k0;
            const int ay = CONV ? (arowBase + (k0 >> 10)) : arowBase;
            tma2d(sbase + c * STAGEB, tmA, ax, ay, mb);
            tma2d(sbase + c * STAGEB + TILEB, tmB, k0, col0, mb);
        }
    }

    // warp grid 2x2, warp tile 64x64
    const int wm = (wid >> 1) * 64;
    const int wn = (wid & 1) * 64;
    const uint32_t aBase = (uint32_t)((wm + (lane & 15)) * 128 + ((lane >> 4) << 4));
    const uint32_t bBase = (uint32_t)((wn + (lane & 7) + ((lane >> 4) << 3)) * 128 +
                                      (((lane >> 3) & 1) << 4));

    float acc[4][8][4];
#pragma unroll
    for (int i = 0; i < 4; i++)
#pragma unroll
        for (int j = 0; j < 8; j++)
#pragma unroll
            for (int e = 0; e < 4; e++) acc[i][j][e] = 0.0f;

    for (int c = 0; c < kChunks; c++) {
        __syncthreads();   // all warps done with chunk c-1 -> stage (c+2)%3 reusable

        if (tid == 0 && c + 2 < kChunks) {
            const int c2 = c + 2;
            const int s2 = c2 % 3;
            const int k0 = c2 * BK;
            const uint32_t mb = mbars + s2 * 8;
            mbar_expect(mb, 2 * TILEB);
            const int ax = CONV ? (k0 & 1023) : k0;
            const int ay = CONV ? (arowBase + (k0 >> 10)) : arowBase;
            tma2d(sbase + s2 * STAGEB, tmA, ax, ay, mb);
            tma2d(sbase + s2 * STAGEB + TILEB, tmB, k0, col0, mb);
        }

        const int s = c % 3;
        mbar_wait(mbars + s * 8, (uint32_t)((c / 3) & 1));

        const uint32_t stA = sbase + s * STAGEB;
        const uint32_t stB = stA + TILEB;
#pragma unroll
        for (int kk = 0; kk < 4; kk++) {
            uint32_t af[4][4];
#pragma unroll
            for (int mt = 0; mt < 4; mt++) {
                const uint32_t lo = aBase + mt * (16 * 128) + kk * 32;
                ldm_x4(af[mt][0], af[mt][1], af[mt][2], af[mt][3], stA + sw128(lo));
            }
            uint32_t bf[8][2];
#pragma unroll
            for (int nt2 = 0; nt2 < 4; nt2++) {
                const uint32_t lo = bBase + nt2 * (16 * 128) + kk * 32;
                ldm_x4(bf[2 * nt2][0], bf[2 * nt2][1], bf[2 * nt2 + 1][0], bf[2 * nt2 + 1][1],
                       stB + sw128(lo));
            }
#pragma unroll
            for (int mt = 0; mt < 4; mt++)
#pragma unroll
                for (int nt = 0; nt < 8; nt++)
                    mma16816(acc[mt][nt], af[mt], bf[nt]);
        }
    }

    // ---- epilogue: warp writes 64 rows x 64 cols
    const int g = lane >> 2, t4 = lane & 3;
#pragma unroll
    for (int mt = 0; mt < 4; mt++) {
        const int m = row0 + wm + mt * 16 + g;
        OT* crow0 = C + (size_t)m * HH;
        OT* crow1 = crow0 + 8 * HH;
#pragma unroll
        for (int nt = 0; nt < 8; nt++) {
            const int n = col0 + wn + nt * 8 + 2 * t4;
            const float b0 = bias[n], b1 = bias[n + 1];
            float v0 = acc[mt][nt][0] + b0;
            float v1 = acc[mt][nt][1] + b1;
            float v2 = acc[mt][nt][2] + b0;
            float v3 = acc[mt][nt][3] + b1;
            if (GELU) {
                v0 = gelu_exact(v0); v1 = gelu_exact(v1);
                v2 = gelu_exact(v2); v3 = gelu_exact(v3);
            }
            if (sizeof(OT) == 2) {
                __half2* p0 = (__half2*)(crow0 + n);
                __half2* p1 = (__half2*)(crow1 + n);
                *p0 = __floats2half2_rn(v0, v1);
                *p1 = __floats2half2_rn(v2, v3);
            } else {
                *(float2*)((float*)crow0 + n) = make_float2(v0, v1);
                *(float2*)((float*)crow1 + n) = make_float2(v2, v3);
            }
        }
    }
}

// conv GEMMs merged: grid.z selects approx (0) / detail (1)
__global__ __launch_bounds__(128, 2)
void conv_gemm(const __grid_constant__ CUtensorMap tmAca,
               const __grid_constant__ CUtensorMap tmAcd,
               const __grid_constant__ CUtensorMap tmBa,
               const __grid_constant__ CUtensorMap tmBd,
               const float* __restrict__ bias_a, const float* __restrict__ bias_d) {
    extern __shared__ __align__(1024) char smem[];
    const int which = blockIdx.z;
    const CUtensorMap* tA = which ? &tmAcd : &tmAca;
    const CUtensorMap* tB = which ? &tmBd : &tmBa;
    const float* bias = which ? bias_d : bias_a;
    __half* C = which ? g_pd : g_pa;
    gemm_body<true, true, __half>(tA, tB, bias, C, 48, smem);
}

__global__ __launch_bounds__(128, 2)
void out_gemm(const __grid_constant__ CUtensorMap tmA,
              const __grid_constant__ CUtensorMap tmB,
              const float* __restrict__ b_out, float* __restrict__ out) {
    extern __shared__ __align__(1024) char smem[];
    gemm_body<false, false, float>(&tmA, &tmB, b_out, out, 16, smem);
}

// ---------------------------------------------------------------------------
typedef CUresult (*PFN_encode)(
    CUtensorMap*, CUtensorMapDataType, cuuint32_t, void*,
    const cuuint64_t*, const cuuint64_t*, const cuuint32_t*, const cuuint32_t*,
    CUtensorMapInterleave, CUtensorMapSwizzle, CUtensorMapL2promotion,
    CUtensorMapFloatOOBfill);

static void enc2d(PFN_encode enc, CUtensorMap* tm, void* base,
                  unsigned long long inner, unsigned long long rows) {
    cuuint64_t dims[2] = {inner, rows};
    cuuint64_t strides[1] = {inner * 2};
    cuuint32_t box[2] = {64, 128};
    cuuint32_t es[2] = {1, 1};
    enc(tm, CU_TENSOR_MAP_DATA_TYPE_UINT16, 2, base, dims, strides, box, es,
        CU_TENSOR_MAP_INTERLEAVE_NONE, CU_TENSOR_MAP_SWIZZLE_128B,
        CU_TENSOR_MAP_L2_PROMOTION_L2_128B, CU_TENSOR_MAP_FLOAT_OOB_FILL_NONE);
}

extern "C" void kernel_launch(void* const* d_in, const int* in_sizes, int n_in,
                              void* d_out, int out_size) {
    const float* x        = (const float*)d_in[0];
    const float* w_approx = (const float*)d_in[1];
    const float* b_approx = (const float*)d_in[2];
    const float* w_detail = (const float*)d_in[3];
    const float* b_detail = (const float*)d_in[4];
    const float* w_out    = (const float*)d_in[5];
    const float* b_out    = (const float*)d_in[6];
    float* out = (float*)d_out;

    cudaFuncSetAttribute(conv_gemm, cudaFuncAttributeMaxDynamicSharedMemorySize, SMEM_BYTES);
    cudaFuncSetAttribute(out_gemm, cudaFuncAttributeMaxDynamicSharedMemorySize, SMEM_BYTES);

    void *p_ca, *p_cd, *p_rec, *p_wc, *p_wo;
    cudaGetSymbolAddress(&p_ca, g_ca);
    cudaGetSymbolAddress(&p_cd, g_cd);
    cudaGetSymbolAddress(&p_rec, g_rec);
    cudaGetSymbolAddress(&p_wc, g_wc);
    cudaGetSymbolAddress(&p_wo, g_wo);

    void* fn = nullptr;
    cudaDriverEntryPointQueryResult qr;
    cudaGetDriverEntryPoint("cuTensorMapEncodeTiled", &fn, cudaEnableDefault, &qr);
    PFN_encode enc = (PFN_encode)fn;

    CUtensorMap tmAca, tmAcd, tmBa, tmBd, tmArec, tmBo;
    enc2d(enc, &tmAca, p_ca, 1024, (unsigned long long)NB * MP);
    enc2d(enc, &tmAcd, p_cd, 1024, (unsigned long long)NB * MP);
    enc2d(enc, &tmBa, p_wc, 3072, 1024);
    enc2d(enc, &tmBd, (char*)p_wc + (size_t)HH * 3072 * 2, 3072, 1024);
    enc2d(enc, &tmArec, p_rec, 1024, (unsigned long long)NB * SS);
    enc2d(enc, &tmBo, p_wo, 1024, 1024);

    prep_conv_w<<<8192, 256>>>(w_approx, w_detail);
    prep_out_w<<<4096, 256>>>(w_out);
    zero_pad_kernel<<<16, 256>>>();
    dwt_kernel<<<NB * MM, 256>>>(x);

    // conv GEMMs: M=8192, N=1024, K=3072, both halves in one launch
    conv_gemm<<<dim3(8, 64, 2), 128, SMEM_BYTES>>>(tmAca, tmAcd, tmBa, tmBd,
                                                   b_approx, b_detail);

    idwt_kernel<<<NB * SS, 256>>>();

    // out GEMM: M=16384, N=1024, K=1024
    out_gemm<<<dim3(8, 128), 128, SMEM_BYTES>>>(tmArec, tmBo, b_out, out);
}

// round 9
// speedup vs baseline: 1.0182x; 1.0182x over previous
#include <cuda_runtime.h>
#include <cuda.h>
#include <cuda_fp16.h>
#include <math.h>
#include <stdint.h>

#define NB 8
#define SS 2048
#define HH 1024
#define MM 1024
#define MP 1026   // padded rows per batch (zero row below m=0 and above m=1023)

#define C_H0 0.48296291314469025f
#define C_H1 0.83651630373780790f
#define C_H2 0.22414386804185735f
#define C_H3 (-0.12940952255092145f)

// GEMM tiling: CTA 128x128, BK=64, 3-stage TMA pipeline, SW128
// 8 warps (256 threads), warp tile 64x32 (2x4 warp grid)
#define BK 64
#define NWARPS 8
#define TILEB 16384           // 128 rows x 128B per operand tile
#define STAGEB (2 * TILEB)    // A + B
#define SMEM_BYTES (3 * STAGEB + 64)

// ---------------- device scratch ----------------
__device__ __align__(16) __half g_ca[NB * MP * HH];
__device__ __align__(16) __half g_cd[NB * MP * HH];
__device__ __align__(16) __half g_pa[NB * MM * HH];
__device__ __align__(16) __half g_pd[NB * MM * HH];
__device__ __align__(16) __half g_rec[NB * SS * HH];
__device__ __align__(16) __half g_wc[2 * HH * 3072];  // [which][o][delta*1024+h]
__device__ __align__(16) __half g_wo[HH * HH];        // [o][h]

// ---------------- helpers ----------------
__device__ __forceinline__ uint32_t smem_u32(const void* p) {
    uint32_t a;
    asm("{ .reg .u64 t; cvta.to.shared.u64 t, %1; cvt.u32.u64 %0, t; }" : "=r"(a) : "l"(p));
    return a;
}

__device__ __forceinline__ uint32_t sw128(uint32_t o) {  // SW128: bits[6:4] ^= bits[9:7]
    return o ^ ((o >> 3) & 0x70);
}

__device__ __forceinline__ void ldm_x4(uint32_t& r0, uint32_t& r1, uint32_t& r2, uint32_t& r3,
                                       uint32_t addr) {
    asm volatile("ldmatrix.sync.aligned.m8n8.x4.shared.b16 {%0,%1,%2,%3}, [%4];"
                 : "=r"(r0), "=r"(r1), "=r"(r2), "=r"(r3) : "r"(addr));
}

__device__ __forceinline__ void mma16816(float* d, const uint32_t* a, const uint32_t* b) {
    asm volatile(
        "mma.sync.aligned.m16n8k16.row.col.f32.f16.f16.f32 "
        "{%0,%1,%2,%3}, {%4,%5,%6,%7}, {%8,%9}, {%0,%1,%2,%3};"
        : "+f"(d[0]), "+f"(d[1]), "+f"(d[2]), "+f"(d[3])
        : "r"(a[0]), "r"(a[1]), "r"(a[2]), "r"(a[3]), "r"(b[0]), "r"(b[1]));
}

__device__ __forceinline__ void tma2d(uint32_t dst, const CUtensorMap* tm, int x, int y,
                                      uint32_t mb) {
    asm volatile(
        "cp.async.bulk.tensor.2d.shared::cta.global.tile.mbarrier::complete_tx::bytes "
        "[%0], [%1, {%2, %3}], [%4];"
        :: "r"(dst), "l"(tm), "r"(x), "r"(y), "r"(mb) : "memory");
}

__device__ __forceinline__ void mbar_init(uint32_t mb, uint32_t cnt) {
    asm volatile("mbarrier.init.shared.b64 [%0], %1;" :: "r"(mb), "r"(cnt) : "memory");
}

__device__ __forceinline__ void mbar_expect(uint32_t mb, uint32_t bytes) {
    asm volatile("mbarrier.arrive.expect_tx.shared.b64 _, [%0], %1;"
                 :: "r"(mb), "r"(bytes) : "memory");
}

__device__ __forceinline__ void mbar_arrive(uint32_t mb) {
    asm volatile("mbarrier.arrive.release.cta.shared::cta.b64 _, [%0];"
                 :: "r"(mb) : "memory");
}

__device__ __forceinline__ void mbar_wait(uint32_t mb, uint32_t parity) {
    asm volatile(
        "{\n\t.reg .pred P;\n\t"
        "LAB_%=:\n\t"
        "mbarrier.try_wait.parity.acquire.cta.shared::cta.b64 P, [%0], %1, 0x989680;\n\t"
        "@!P bra LAB_%=;\n\t"
        "}" :: "r"(mb), "r"(parity) : "memory");
}

__device__ __forceinline__ float gelu_exact(float v) {
    return 0.5f * v * (1.0f + erff(v * 0.70710678118654752f));
}

// ---------------- weight prep (fused: conv + out weights) ----------------
__global__ void prep_weights(const float* __restrict__ wA, const float* __restrict__ wD,
                             const float* __restrict__ wO) {
    int idx = blockIdx.x * 256 + threadIdx.x;
    if (idx < (2 << 20)) {                   // conv weights: 2 * 1M entries (o,h)
        int which = idx >> 20;
        int oh = idx & ((1 << 20) - 1);
        int o = oh >> 10, h = oh & 1023;
        const float* w = which ? wD : wA;
        __half* W = g_wc + (size_t)which * HH * 3072;
        const float* p = w + ((size_t)o * HH + h) * 3;
#pragma unroll
        for (int d = 0; d < 3; d++)
            W[(size_t)o * 3072 + d * 1024 + h] = __float2half_rn(p[d]);
    } else {                                 // out weights: 1M entries
        int j = idx - (2 << 20);
        g_wo[j] = __float2half_rn(wO[j]);
    }
}

// ---------------- DWT -> fp16 (padded rows) + boundary zero rows ----------------
__global__ void dwt_kernel(const float* __restrict__ x) {
    int bm = blockIdx.x;
    if (bm >= NB * MM) {                     // 16 extra blocks: zero pad rows
        int j = bm - NB * MM;
        int b = j >> 1;
        int top = j & 1;
        size_t off = ((size_t)b * MP + (top ? 1025 : 0)) * HH + threadIdx.x * 4;
        uint2 z = make_uint2(0u, 0u);
        *(uint2*)(g_ca + off) = z;
        *(uint2*)(g_cd + off) = z;
        return;
    }
    int b = bm >> 10, m = bm & 1023;
    int h = threadIdx.x << 2;
    int s0 = 2 * m - 2, s1 = 2 * m - 1;
    if (s0 < 0) s0 = -s0 - 1;
    if (s1 < 0) s1 = -s1 - 1;
    const float* xb = x + (size_t)b * SS * HH + h;
    float4 v0 = *(const float4*)(xb + (size_t)s0 * HH);
    float4 v1 = *(const float4*)(xb + (size_t)s1 * HH);
    float4 v2 = *(const float4*)(xb + (size_t)(2 * m) * HH);
    float4 v3 = *(const float4*)(xb + (size_t)(2 * m + 1) * HH);
    __half ca[4], cd[4];
    ca[0] = __float2half_rn(C_H0 * v0.x + C_H1 * v1.x + C_H2 * v2.x + C_H3 * v3.x);
    ca[1] = __float2half_rn(C_H0 * v0.y + C_H1 * v1.y + C_H2 * v2.y + C_H3 * v3.y);
    ca[2] = __float2half_rn(C_H0 * v0.z + C_H1 * v1.z + C_H2 * v2.z + C_H3 * v3.z);
    ca[3] = __float2half_rn(C_H0 * v0.w + C_H1 * v1.w + C_H2 * v2.w + C_H3 * v3.w);
    cd[0] = __float2half_rn(C_H3 * v0.x - C_H2 * v1.x + C_H1 * v2.x - C_H0 * v3.x);
    cd[1] = __float2half_rn(C_H3 * v0.y - C_H2 * v1.y + C_H1 * v2.y - C_H0 * v3.y);
    cd[2] = __float2half_rn(C_H3 * v0.z - C_H2 * v1.z + C_H1 * v2.z - C_H0 * v3.z);
    cd[3] = __float2half_rn(C_H3 * v0.w - C_H2 * v1.w + C_H1 * v2.w - C_H0 * v3.w);
    size_t off = ((size_t)b * MP + m + 1) * HH + h;
    *(uint2*)(g_ca + off) = *(const uint2*)ca;
    *(uint2*)(g_cd + off) = *(const uint2*)cd;
}

// ---------------- iDWT: fp16 pa/pd -> fp16 recon ----------------
__global__ void idwt_kernel() {
    int bn = blockIdx.x;
    int b = bn >> 11, n = bn & 2047;
    int h = threadIdx.x << 2;
    size_t outoff = ((size_t)b * SS + n) * HH + h;
    if (n >= 2046) {
        *(uint2*)(g_rec + outoff) = make_uint2(0u, 0u);
        return;
    }
    int m0, m1;
    float wa0, wa1, wd0, wd1;
    if (!(n & 1)) {
        m0 = n >> 1; m1 = m0 + 1;
        wa1 = C_H0; wa0 = C_H2; wd1 = C_H3; wd0 = C_H1;
    } else {
        m0 = (n - 1) >> 1; m1 = m0 + 1;
        wa1 = C_H1; wa0 = C_H3; wd1 = -C_H2; wd0 = -C_H0;
    }
    size_t base = (size_t)b * MM * HH + h;
    uint2 ua0 = *(const uint2*)(g_pa + base + (size_t)m0 * HH);
    uint2 ua1 = *(const uint2*)(g_pa + base + (size_t)m1 * HH);
    uint2 ud0 = *(const uint2*)(g_pd + base + (size_t)m0 * HH);
    uint2 ud1 = *(const uint2*)(g_pd + base + (size_t)m1 * HH);
    const __half2* a0 = (const __half2*)&ua0;
    const __half2* a1 = (const __half2*)&ua1;
    const __half2* d0 = (const __half2*)&ud0;
    const __half2* d1 = (const __half2*)&ud1;
    __half rv[4];
#pragma unroll
    for (int q = 0; q < 2; q++) {
        float2 fa0 = __half22float2(a0[q]);
        float2 fa1 = __half22float2(a1[q]);
        float2 fd0 = __half22float2(d0[q]);
        float2 fd1 = __half22float2(d1[q]);
        rv[2 * q + 0] = __float2half_rn(wa0 * fa0.x + wa1 * fa1.x + wd0 * fd0.x + wd1 * fd1.x);
        rv[2 * q + 1] = __float2half_rn(wa0 * fa0.y + wa1 * fa1.y + wd0 * fd0.y + wd1 * fd1.y);
    }
    *(uint2*)(g_rec + outoff) = *(const uint2*)rv;
}

// ---------------------------------------------------------------------------
// fp16 GEMM body, TMA-fed, full/empty mbarrier pipeline (no per-chunk syncthreads):
// C[M,1024] = A[M,K] * B[1024,K]^T (+bias, opt GELU)
// 256 threads, 2x4 warp grid, warp tile 64x32. 3 stages, BK=64, SW128.
// full[s]: tx-barrier (TMA completion). empty[s]: count=NWARPS (stage consumed).
// RACE FIX (R8->R9): __syncwarp() before the elected empty-arrive so ALL lanes'
// ldmatrix reads are ordered before the release.
// ---------------------------------------------------------------------------
template <bool CONV, bool GELU, typename OT>
__device__ __forceinline__ void gemm_body(
    const CUtensorMap* __restrict__ tmA, const CUtensorMap* __restrict__ tmB,
    const float* __restrict__ bias, OT* __restrict__ C,
    int kChunks, char* smem) {

    const uint32_t sbase = smem_u32(smem);
    const uint32_t fullb = sbase + 3 * STAGEB;   // full[0..2] at +0,8,16
    const uint32_t emptyb = fullb + 24;          // empty[0..2] at +0,8,16

    const int tid = threadIdx.x;
    const int lane = tid & 31;
    const int wid = tid >> 5;
    const int row0 = blockIdx.y << 7;
    const int col0 = blockIdx.x << 7;
    const int arowBase = CONV ? ((row0 >> 10) * MP + (row0 & 1023)) : row0;

    if (tid == 0) {
#pragma unroll
        for (int s = 0; s < 3; s++) {
            mbar_init(fullb + s * 8, 1);
            mbar_init(emptyb + s * 8, NWARPS);
        }
    }
    __syncthreads();

    // prologue: issue chunks 0,1 (stage use u=0 -> no empty wait)
    if (tid == 0) {
#pragma unroll
        for (int c = 0; c < 2; c++) {
            const int k0 = c * BK;
            const uint32_t mb = fullb + c * 8;
            mbar_expect(mb, 2 * TILEB);
            const int ax = CONV ? (k0 & 1023) : k0;
            const int ay = CONV ? (arowBase + (k0 >> 10)) : arowBase;
            tma2d(sbase + c * STAGEB, tmA, ax, ay, mb);
            tma2d(sbase + c * STAGEB + TILEB, tmB, k0, col0, mb);
        }
    }

    // warp grid 2x4, warp tile 64x32
    const int wm = (wid >> 2) * 64;
    const int wn = (wid & 3) * 32;
    const uint32_t aBase = (uint32_t)((wm + (lane & 15)) * 128 + ((lane >> 4) << 4));
    const uint32_t bBase = (uint32_t)((wn + (lane & 7) + ((lane >> 4) << 3)) * 128 +
                                      (((lane >> 3) & 1) << 4));

    float acc[4][4][4];
#pragma unroll
    for (int i = 0; i < 4; i++)
#pragma unroll
        for (int j = 0; j < 4; j++)
#pragma unroll
            for (int e = 0; e < 4; e++) acc[i][j][e] = 0.0f;

    for (int c = 0; c < kChunks; c++) {
        // producer: issue chunk c+2 into stage (c+2)%3 once that stage is drained
        if (tid == 0 && c + 2 < kChunks) {
            const int c2 = c + 2;
            const int s2 = c2 % 3;
            const int u2 = c2 / 3;                       // use index of this stage
            if (u2 > 0) mbar_wait(emptyb + s2 * 8, (uint32_t)((u2 - 1) & 1));
            const int k0 = c2 * BK;
            const uint32_t mb = fullb + s2 * 8;
            mbar_expect(mb, 2 * TILEB);
            const int ax = CONV ? (k0 & 1023) : k0;
            const int ay = CONV ? (arowBase + (k0 >> 10)) : arowBase;
            tma2d(sbase + s2 * STAGEB, tmA, ax, ay, mb);
            tma2d(sbase + s2 * STAGEB + TILEB, tmB, k0, col0, mb);
        }

        const int s = c % 3;
        mbar_wait(fullb + s * 8, (uint32_t)((c / 3) & 1));

        const uint32_t stA = sbase + s * STAGEB;
        const uint32_t stB = stA + TILEB;
#pragma unroll
        for (int kk = 0; kk < 4; kk++) {
            uint32_t af[4][4];
#pragma unroll
            for (int mt = 0; mt < 4; mt++) {
                const uint32_t lo = aBase + mt * (16 * 128) + kk * 32;
                ldm_x4(af[mt][0], af[mt][1], af[mt][2], af[mt][3], stA + sw128(lo));
            }
            uint32_t bf[4][2];
#pragma unroll
            for (int nt2 = 0; nt2 < 2; nt2++) {
                const uint32_t lo = bBase + nt2 * (16 * 128) + kk * 32;
                ldm_x4(bf[2 * nt2][0], bf[2 * nt2][1], bf[2 * nt2 + 1][0], bf[2 * nt2 + 1][1],
                       stB + sw128(lo));
            }
#pragma unroll
            for (int mt = 0; mt < 4; mt++)
#pragma unroll
                for (int nt = 0; nt < 4; nt++)
                    mma16816(acc[mt][nt], af[mt], bf[nt]);
        }

        // order ALL lanes' smem reads before the elected release-arrive
        __syncwarp();
        if (lane == 0) mbar_arrive(emptyb + s * 8);
    }

    // ---- epilogue: warp writes 64 rows x 32 cols
    const int g = lane >> 2, t4 = lane & 3;
#pragma unroll
    for (int mt = 0; mt < 4; mt++) {
        const int m = row0 + wm + mt * 16 + g;
        OT* crow0 = C + (size_t)m * HH;
        OT* crow1 = crow0 + 8 * HH;
#pragma unroll
        for (int nt = 0; nt < 4; nt++) {
            const int n = col0 + wn + nt * 8 + 2 * t4;
            const float b0 = bias[n], b1 = bias[n + 1];
            float v0 = acc[mt][nt][0] + b0;
            float v1 = acc[mt][nt][1] + b1;
            float v2 = acc[mt][nt][2] + b0;
            float v3 = acc[mt][nt][3] + b1;
            if (GELU) {
                v0 = gelu_exact(v0); v1 = gelu_exact(v1);
                v2 = gelu_exact(v2); v3 = gelu_exact(v3);
            }
            if (sizeof(OT) == 2) {
                *(__half2*)(crow0 + n) = __floats2half2_rn(v0, v1);
                *(__half2*)(crow1 + n) = __floats2half2_rn(v2, v3);
            } else {
                *(float2*)((float*)crow0 + n) = make_float2(v0, v1);
                *(float2*)((float*)crow1 + n) = make_float2(v2, v3);
            }
        }
    }
}

// conv GEMMs merged: grid.z selects approx (0) / detail (1)
__global__ __launch_bounds__(256, 2)
void conv_gemm(const __grid_constant__ CUtensorMap tmAca,
               const __grid_constant__ CUtensorMap tmAcd,
               const __grid_constant__ CUtensorMap tmBa,
               const __grid_constant__ CUtensorMap tmBd,
               const float* __restrict__ bias_a, const float* __restrict__ bias_d) {
    extern __shared__ __align__(1024) char smem[];
    const int which = blockIdx.z;
    const CUtensorMap* tA = which ? &tmAcd : &tmAca;
    const CUtensorMap* tB = which ? &tmBd : &tmBa;
    const float* bias = which ? bias_d : bias_a;
    __half* C = which ? g_pd : g_pa;
    gemm_body<true, true, __half>(tA, tB, bias, C, 48, smem);
}

__global__ __launch_bounds__(256, 2)
void out_gemm(const __grid_constant__ CUtensorMap tmA,
              const __grid_constant__ CUtensorMap tmB,
              const float* __restrict__ b_out, float* __restrict__ out) {
    extern __shared__ __align__(1024) char smem[];
    gemm_body<false, false, float>(&tmA, &tmB, b_out, out, 16, smem);
}

// ---------------------------------------------------------------------------
typedef CUresult (*PFN_encode)(
    CUtensorMap*, CUtensorMapDataType, cuuint32_t, void*,
    const cuuint64_t*, const cuuint64_t*, const cuuint32_t*, const cuuint32_t*,
    CUtensorMapInterleave, CUtensorMapSwizzle, CUtensorMapL2promotion,
    CUtensorMapFloatOOBfill);

static void enc2d(PFN_encode enc, CUtensorMap* tm, void* base,
                  unsigned long long inner, unsigned long long rows) {
    cuuint64_t dims[2] = {inner, rows};
    cuuint64_t strides[1] = {inner * 2};
    cuuint32_t box[2] = {64, 128};
    cuuint32_t es[2] = {1, 1};
    enc(tm, CU_TENSOR_MAP_DATA_TYPE_UINT16, 2, base, dims, strides, box, es,
        CU_TENSOR_MAP_INTERLEAVE_NONE, CU_TENSOR_MAP_SWIZZLE_128B,
        CU_TENSOR_MAP_L2_PROMOTION_L2_128B, CU_TENSOR_MAP_FLOAT_OOB_FILL_NONE);
}

extern "C" void kernel_launch(void* const* d_in, const int* in_sizes, int n_in,
                              void* d_out, int out_size) {
    const float* x        = (const float*)d_in[0];
    const float* w_approx = (const float*)d_in[1];
    const float* b_approx = (const float*)d_in[2];
    const float* w_detail = (const float*)d_in[3];
    const float* b_detail = (const float*)d_in[4];
    const float* w_out    = (const float*)d_in[5];
    const float* b_out    = (const float*)d_in[6];
    float* out = (float*)d_out;

    cudaFuncSetAttribute(conv_gemm, cudaFuncAttributeMaxDynamicSharedMemorySize, SMEM_BYTES);
    cudaFuncSetAttribute(out_gemm, cudaFuncAttributeMaxDynamicSharedMemorySize, SMEM_BYTES);

    void *p_ca, *p_cd, *p_rec, *p_wc, *p_wo;
    cudaGetSymbolAddress(&p_ca, g_ca);
    cudaGetSymbolAddress(&p_cd, g_cd);
    cudaGetSymbolAddress(&p_rec, g_rec);
    cudaGetSymbolAddress(&p_wc, g_wc);
    cudaGetSymbolAddress(&p_wo, g_wo);

    void* fn = nullptr;
    cudaDriverEntryPointQueryResult qr;
    cudaGetDriverEntryPoint("cuTensorMapEncodeTiled", &fn, cudaEnableDefault, &qr);
    PFN_encode enc = (PFN_encode)fn;

    CUtensorMap tmAca, tmAcd, tmBa, tmBd, tmArec, tmBo;
    enc2d(enc, &tmAca, p_ca, 1024, (unsigned long long)NB * MP);
    enc2d(enc, &tmAcd, p_cd, 1024, (unsigned long long)NB * MP);
    enc2d(enc, &tmBa, p_wc, 3072, 1024);
    enc2d(enc, &tmBd, (char*)p_wc + (size_t)HH * 3072 * 2, 3072, 1024);
    enc2d(enc, &tmArec, p_rec, 1024, (unsigned long long)NB * SS);
    enc2d(enc, &tmBo, p_wo, 1024, 1024);

    // fused weight prep: 8192 blocks conv + 4096 blocks out
    prep_weights<<<12288, 256>>>(w_approx, w_detail, w_out);
    // fused DWT + zero-pad
    dwt_kernel<<<NB * MM + 16, 256>>>(x);

    // conv GEMMs: M=8192, N=1024, K=3072, both halves in one launch
    conv_gemm<<<dim3(8, 64, 2), 256, SMEM_BYTES>>>(tmAca, tmAcd, tmBa, tmBd,
                                                   b_approx, b_detail);

    idwt_kernel<<<NB * SS, 256>>>();

    // out GEMM: M=16384, N=1024, K=1024
    out_gemm<<<dim3(8, 128), 256, SMEM_BYTES>>>(tmArec, tmBo, b_out, out);
}

// round 10
// speedup vs baseline: 1.0750x; 1.0558x over previous
#include <cuda_runtime.h>
#include <cuda.h>
#include <cuda_fp16.h>
#include <math.h>
#include <stdint.h>

#define NB 8
#define SS 2048
#define HH 1024
#define MM 1024
#define MP 1026   // padded rows per batch (zero row below m=0 and above m=1023)

#define C_H0 0.48296291314469025f
#define C_H1 0.83651630373780790f
#define C_H2 0.22414386804185735f
#define C_H3 (-0.12940952255092145f)

// GEMM tiling: CTA 128x128, BK=64, 3-stage TMA pipeline, SW128
// 8 warps (256 threads), warp tile 64x32 (2x4 warp grid)
#define BK 64
#define TILEB 16384           // 128 rows x 128B per operand tile
#define STAGEB (2 * TILEB)    // A + B
#define SMEM_BYTES (3 * STAGEB + 64)

// ---------------- device scratch ----------------
__device__ __align__(16) __half g_ca[NB * MP * HH];
__device__ __align__(16) __half g_cd[NB * MP * HH];
__device__ __align__(16) __half g_pa[NB * MM * HH];
__device__ __align__(16) __half g_pd[NB * MM * HH];
__device__ __align__(16) __half g_rec[NB * SS * HH];
__device__ __align__(16) __half g_wc[2 * HH * 3072];  // [which][o][delta*1024+h]
__device__ __align__(16) __half g_wo[HH * HH];        // [o][h]

// ---------------- helpers ----------------
__device__ __forceinline__ uint32_t smem_u32(const void* p) {
    uint32_t a;
    asm("{ .reg .u64 t; cvta.to.shared.u64 t, %1; cvt.u32.u64 %0, t; }" : "=r"(a) : "l"(p));
    return a;
}

__device__ __forceinline__ uint32_t sw128(uint32_t o) {  // SW128: bits[6:4] ^= bits[9:7]
    return o ^ ((o >> 3) & 0x70);
}

__device__ __forceinline__ void ldm_x4(uint32_t& r0, uint32_t& r1, uint32_t& r2, uint32_t& r3,
                                       uint32_t addr) {
    asm volatile("ldmatrix.sync.aligned.m8n8.x4.shared.b16 {%0,%1,%2,%3}, [%4];"
                 : "=r"(r0), "=r"(r1), "=r"(r2), "=r"(r3) : "r"(addr));
}

__device__ __forceinline__ void mma16816(float* d, const uint32_t* a, const uint32_t* b) {
    asm volatile(
        "mma.sync.aligned.m16n8k16.row.col.f32.f16.f16.f32 "
        "{%0,%1,%2,%3}, {%4,%5,%6,%7}, {%8,%9}, {%0,%1,%2,%3};"
        : "+f"(d[0]), "+f"(d[1]), "+f"(d[2]), "+f"(d[3])
        : "r"(a[0]), "r"(a[1]), "r"(a[2]), "r"(a[3]), "r"(b[0]), "r"(b[1]));
}

__device__ __forceinline__ void tma2d(uint32_t dst, const CUtensorMap* tm, int x, int y,
                                      uint32_t mb) {
    asm volatile(
        "cp.async.bulk.tensor.2d.shared::cta.global.tile.mbarrier::complete_tx::bytes "
        "[%0], [%1, {%2, %3}], [%4];"
        :: "r"(dst), "l"(tm), "r"(x), "r"(y), "r"(mb) : "memory");
}

__device__ __forceinline__ void mbar_init(uint32_t mb, uint32_t cnt) {
    asm volatile("mbarrier.init.shared.b64 [%0], %1;" :: "r"(mb), "r"(cnt) : "memory");
}

__device__ __forceinline__ void mbar_expect(uint32_t mb, uint32_t bytes) {
    asm volatile("mbarrier.arrive.expect_tx.shared.b64 _, [%0], %1;"
                 :: "r"(mb), "r"(bytes) : "memory");
}

__device__ __forceinline__ void mbar_wait(uint32_t mb, uint32_t parity) {
    asm volatile(
        "{\n\t.reg .pred P;\n\t"
        "LAB_%=:\n\t"
        "mbarrier.try_wait.parity.acquire.cta.shared::cta.b64 P, [%0], %1, 0x989680;\n\t"
        "@!P bra LAB_%=;\n\t"
        "}" :: "r"(mb), "r"(parity) : "memory");
}

__device__ __forceinline__ float gelu_exact(float v) {
    return 0.5f * v * (1.0f + erff(v * 0.70710678118654752f));
}

// ---------------- weight prep (fused: conv + out weights) ----------------
__global__ void prep_weights(const float* __restrict__ wA, const float* __restrict__ wD,
                             const float* __restrict__ wO) {
    int idx = blockIdx.x * 256 + threadIdx.x;
    if (idx < (2 << 20)) {                   // conv weights: 2 * 1M entries (o,h)
        int which = idx >> 20;
        int oh = idx & ((1 << 20) - 1);
        int o = oh >> 10, h = oh & 1023;
        const float* w = which ? wD : wA;
        __half* W = g_wc + (size_t)which * HH * 3072;
        const float* p = w + ((size_t)o * HH + h) * 3;
#pragma unroll
        for (int d = 0; d < 3; d++)
            W[(size_t)o * 3072 + d * 1024 + h] = __float2half_rn(p[d]);
    } else {                                 // out weights: 1M entries
        int j = idx - (2 << 20);
        g_wo[j] = __float2half_rn(wO[j]);
    }
}

// ---------------- DWT -> fp16 (padded rows) + boundary zero rows ----------------
__global__ void dwt_kernel(const float* __restrict__ x) {
    int bm = blockIdx.x;
    if (bm >= NB * MM) {                     // 16 extra blocks: zero pad rows
        int j = bm - NB * MM;
        int b = j >> 1;
        int top = j & 1;
        size_t off = ((size_t)b * MP + (top ? 1025 : 0)) * HH + threadIdx.x * 4;
        uint2 z = make_uint2(0u, 0u);
        *(uint2*)(g_ca + off) = z;
        *(uint2*)(g_cd + off) = z;
        return;
    }
    int b = bm >> 10, m = bm & 1023;
    int h = threadIdx.x << 2;
    int s0 = 2 * m - 2, s1 = 2 * m - 1;
    if (s0 < 0) s0 = -s0 - 1;
    if (s1 < 0) s1 = -s1 - 1;
    const float* xb = x + (size_t)b * SS * HH + h;
    float4 v0 = *(const float4*)(xb + (size_t)s0 * HH);
    float4 v1 = *(const float4*)(xb + (size_t)s1 * HH);
    float4 v2 = *(const float4*)(xb + (size_t)(2 * m) * HH);
    float4 v3 = *(const float4*)(xb + (size_t)(2 * m + 1) * HH);
    __half ca[4], cd[4];
    ca[0] = __float2half_rn(C_H0 * v0.x + C_H1 * v1.x + C_H2 * v2.x + C_H3 * v3.x);
    ca[1] = __float2half_rn(C_H0 * v0.y + C_H1 * v1.y + C_H2 * v2.y + C_H3 * v3.y);
    ca[2] = __float2half_rn(C_H0 * v0.z + C_H1 * v1.z + C_H2 * v2.z + C_H3 * v3.z);
    ca[3] = __float2half_rn(C_H0 * v0.w + C_H1 * v1.w + C_H2 * v2.w + C_H3 * v3.w);
    cd[0] = __float2half_rn(C_H3 * v0.x - C_H2 * v1.x + C_H1 * v2.x - C_H0 * v3.x);
    cd[1] = __float2half_rn(C_H3 * v0.y - C_H2 * v1.y + C_H1 * v2.y - C_H0 * v3.y);
    cd[2] = __float2half_rn(C_H3 * v0.z - C_H2 * v1.z + C_H1 * v2.z - C_H0 * v3.z);
    cd[3] = __float2half_rn(C_H3 * v0.w - C_H2 * v1.w + C_H1 * v2.w - C_H0 * v3.w);
    size_t off = ((size_t)b * MP + m + 1) * HH + h;
    *(uint2*)(g_ca + off) = *(const uint2*)ca;
    *(uint2*)(g_cd + off) = *(const uint2*)cd;
}

// ---------------- paired iDWT: rows 2t and 2t+1 share the same 4 source rows ----
// even (n=2t):   H2*pa[t] + H0*pa[t+1] + H1*pd[t] + H3*pd[t+1]
// odd  (n=2t+1): H3*pa[t] + H1*pa[t+1] - H0*pd[t] - H2*pd[t+1]
__global__ void idwt_kernel() {
    int bt = blockIdx.x;
    int b = bt >> 10, t = bt & 1023;
    int h = threadIdx.x << 2;
    size_t outoff = ((size_t)b * SS + 2 * t) * HH + h;
    if (t == 1023) {   // rows 2046, 2047 are zero
        uint2 z = make_uint2(0u, 0u);
        *(uint2*)(g_rec + outoff) = z;
        *(uint2*)(g_rec + outoff + HH) = z;
        return;
    }
    size_t base = (size_t)b * MM * HH + h + (size_t)t * HH;
    uint2 ua0 = *(const uint2*)(g_pa + base);
    uint2 ua1 = *(const uint2*)(g_pa + base + HH);
    uint2 ud0 = *(const uint2*)(g_pd + base);
    uint2 ud1 = *(const uint2*)(g_pd + base + HH);
    const __half2* a0 = (const __half2*)&ua0;
    const __half2* a1 = (const __half2*)&ua1;
    const __half2* d0 = (const __half2*)&ud0;
    const __half2* d1 = (const __half2*)&ud1;
    __half ev[4], od[4];
#pragma unroll
    for (int q = 0; q < 2; q++) {
        float2 fa0 = __half22float2(a0[q]);
        float2 fa1 = __half22float2(a1[q]);
        float2 fd0 = __half22float2(d0[q]);
        float2 fd1 = __half22float2(d1[q]);
        ev[2 * q + 0] = __float2half_rn(C_H2 * fa0.x + C_H0 * fa1.x + C_H1 * fd0.x + C_H3 * fd1.x);
        ev[2 * q + 1] = __float2half_rn(C_H2 * fa0.y + C_H0 * fa1.y + C_H1 * fd0.y + C_H3 * fd1.y);
        od[2 * q + 0] = __float2half_rn(C_H3 * fa0.x + C_H1 * fa1.x - C_H0 * fd0.x - C_H2 * fd1.x);
        od[2 * q + 1] = __float2half_rn(C_H3 * fa0.y + C_H1 * fa1.y - C_H0 * fd0.y - C_H2 * fd1.y);
    }
    *(uint2*)(g_rec + outoff) = *(const uint2*)ev;
    *(uint2*)(g_rec + outoff + HH) = *(const uint2*)od;
}

// ---------------------------------------------------------------------------
// fp16 GEMM body, TMA-fed, syncthreads-pipelined (R6 scheme):
// C[M,1024] = A[M,K] * B[1024,K]^T (+bias, opt GELU)
// 256 threads, 2x4 warp grid, warp tile 64x32. 3 stages, BK=64, SW128.
// ---------------------------------------------------------------------------
template <bool CONV, bool GELU, typename OT>
__device__ __forceinline__ void gemm_body(
    const CUtensorMap* __restrict__ tmA, const CUtensorMap* __restrict__ tmB,
    const float* __restrict__ bias, OT* __restrict__ C,
    int kChunks, char* smem) {

    const uint32_t sbase = smem_u32(smem);
    const uint32_t mbars = sbase + 3 * STAGEB;

    const int tid = threadIdx.x;
    const int lane = tid & 31;
    const int wid = tid >> 5;
    const int row0 = blockIdx.y << 7;
    const int col0 = blockIdx.x << 7;
    const int arowBase = CONV ? ((row0 >> 10) * MP + (row0 & 1023)) : row0;

    if (tid == 0) {
        mbar_init(mbars + 0, 1);
        mbar_init(mbars + 8, 1);
        mbar_init(mbars + 16, 1);
    }
    __syncthreads();

    // prologue: stages 0,1
    if (tid == 0) {
#pragma unroll
        for (int c = 0; c < 2; c++) {
            const int k0 = c * BK;
            const uint32_t mb = mbars + c * 8;
            mbar_expect(mb, 2 * TILEB);
            const int ax = CONV ? (k0 & 1023) : k0;
            const int ay = CONV ? (arowBase + (k0 >> 10)) : arowBase;
            tma2d(sbase + c * STAGEB, tmA, ax, ay, mb);
            tma2d(sbase + c * STAGEB + TILEB, tmB, k0, col0, mb);
        }
    }

    // warp grid 2x4, warp tile 64x32
    const int wm = (wid >> 2) * 64;
    const int wn = (wid & 3) * 32;
    const uint32_t aBase = (uint32_t)((wm + (lane & 15)) * 128 + ((lane >> 4) << 4));
    const uint32_t bBase = (uint32_t)((wn + (lane & 7) + ((lane >> 4) << 3)) * 128 +
                                      (((lane >> 3) & 1) << 4));

    float acc[4][4][4];
#pragma unroll
    for (int i = 0; i < 4; i++)
#pragma unroll
        for (int j = 0; j < 4; j++)
#pragma unroll
            for (int e = 0; e < 4; e++) acc[i][j][e] = 0.0f;

    for (int c = 0; c < kChunks; c++) {
        __syncthreads();   // all warps done with chunk c-1 -> stage (c+2)%3 reusable

        if (tid == 0 && c + 2 < kChunks) {
            const int c2 = c + 2;
            const int s2 = c2 % 3;
            const int k0 = c2 * BK;
            const uint32_t mb = mbars + s2 * 8;
            mbar_expect(mb, 2 * TILEB);
            const int ax = CONV ? (k0 & 1023) : k0;
            const int ay = CONV ? (arowBase + (k0 >> 10)) : arowBase;
            tma2d(sbase + s2 * STAGEB, tmA, ax, ay, mb);
            tma2d(sbase + s2 * STAGEB + TILEB, tmB, k0, col0, mb);
        }

        const int s = c % 3;
        mbar_wait(mbars + s * 8, (uint32_t)((c / 3) & 1));

        const uint32_t stA = sbase + s * STAGEB;
        const uint32_t stB = stA + TILEB;
#pragma unroll
        for (int kk = 0; kk < 4; kk++) {
            uint32_t af[4][4];
#pragma unroll
            for (int mt = 0; mt < 4; mt++) {
                const uint32_t lo = aBase + mt * (16 * 128) + kk * 32;
                ldm_x4(af[mt][0], af[mt][1], af[mt][2], af[mt][3], stA + sw128(lo));
            }
            uint32_t bf[4][2];
#pragma unroll
            for (int nt2 = 0; nt2 < 2; nt2++) {
                const uint32_t lo = bBase + nt2 * (16 * 128) + kk * 32;
                ldm_x4(bf[2 * nt2][0], bf[2 * nt2][1], bf[2 * nt2 + 1][0], bf[2 * nt2 + 1][1],
                       stB + sw128(lo));
            }
#pragma unroll
            for (int mt = 0; mt < 4; mt++)
#pragma unroll
                for (int nt = 0; nt < 4; nt++)
                    mma16816(acc[mt][nt], af[mt], bf[nt]);
        }
    }

    // ---- epilogue: warp writes 64 rows x 32 cols
    const int g = lane >> 2, t4 = lane & 3;
#pragma unroll
    for (int mt = 0; mt < 4; mt++) {
        const int m = row0 + wm + mt * 16 + g;
        OT* crow0 = C + (size_t)m * HH;
        OT* crow1 = crow0 + 8 * HH;
#pragma unroll
        for (int nt = 0; nt < 4; nt++) {
            const int n = col0 + wn + nt * 8 + 2 * t4;
            const float b0 = bias[n], b1 = bias[n + 1];
            float v0 = acc[mt][nt][0] + b0;
            float v1 = acc[mt][nt][1] + b1;
            float v2 = acc[mt][nt][2] + b0;
            float v3 = acc[mt][nt][3] + b1;
            if (GELU) {
                v0 = gelu_exact(v0); v1 = gelu_exact(v1);
                v2 = gelu_exact(v2); v3 = gelu_exact(v3);
            }
            if (sizeof(OT) == 2) {
                *(__half2*)(crow0 + n) = __floats2half2_rn(v0, v1);
                *(__half2*)(crow1 + n) = __floats2half2_rn(v2, v3);
            } else {
                *(float2*)((float*)crow0 + n) = make_float2(v0, v1);
                *(float2*)((float*)crow1 + n) = make_float2(v2, v3);
            }
        }
    }
}

// conv GEMMs merged: grid.z selects approx (0) / detail (1)
__global__ __launch_bounds__(256, 2)
void conv_gemm(const __grid_constant__ CUtensorMap tmAca,
               const __grid_constant__ CUtensorMap tmAcd,
               const __grid_constant__ CUtensorMap tmBa,
               const __grid_constant__ CUtensorMap tmBd,
               const float* __restrict__ bias_a, const float* __restrict__ bias_d) {
    extern __shared__ __align__(1024) char smem[];
    const int which = blockIdx.z;
    const CUtensorMap* tA = which ? &tmAcd : &tmAca;
    const CUtensorMap* tB = which ? &tmBd : &tmBa;
    const float* bias = which ? bias_d : bias_a;
    __half* C = which ? g_pd : g_pa;
    gemm_body<true, true, __half>(tA, tB, bias, C, 48, smem);
}

__global__ __launch_bounds__(256, 2)
void out_gemm(const __grid_constant__ CUtensorMap tmA,
              const __grid_constant__ CUtensorMap tmB,
              const float* __restrict__ b_out, float* __restrict__ out) {
    extern __shared__ __align__(1024) char smem[];
    gemm_body<false, false, float>(&tmA, &tmB, b_out, out, 16, smem);
}

// ---------------------------------------------------------------------------
typedef CUresult (*PFN_encode)(
    CUtensorMap*, CUtensorMapDataType, cuuint32_t, void*,
    const cuuint64_t*, const cuuint64_t*, const cuuint32_t*, const cuuint32_t*,
    CUtensorMapInterleave, CUtensorMapSwizzle, CUtensorMapL2promotion,
    CUtensorMapFloatOOBfill);

static void enc2d(PFN_encode enc, CUtensorMap* tm, void* base,
                  unsigned long long inner, unsigned long long rows) {
    cuuint64_t dims[2] = {inner, rows};
    cuuint64_t strides[1] = {inner * 2};
    cuuint32_t box[2] = {64, 128};
    cuuint32_t es[2] = {1, 1};
    enc(tm, CU_TENSOR_MAP_DATA_TYPE_UINT16, 2, base, dims, strides, box, es,
        CU_TENSOR_MAP_INTERLEAVE_NONE, CU_TENSOR_MAP_SWIZZLE_128B,
        CU_TENSOR_MAP_L2_PROMOTION_L2_128B, CU_TENSOR_MAP_FLOAT_OOB_FILL_NONE);
}

extern "C" void kernel_launch(void* const* d_in, const int* in_sizes, int n_in,
                              void* d_out, int out_size) {
    const float* x        = (const float*)d_in[0];
    const float* w_approx = (const float*)d_in[1];
    const float* b_approx = (const float*)d_in[2];
    const float* w_detail = (const float*)d_in[3];
    const float* b_detail = (const float*)d_in[4];
    const float* w_out    = (const float*)d_in[5];
    const float* b_out    = (const float*)d_in[6];
    float* out = (float*)d_out;

    cudaFuncSetAttribute(conv_gemm, cudaFuncAttributeMaxDynamicSharedMemorySize, SMEM_BYTES);
    cudaFuncSetAttribute(out_gemm, cudaFuncAttributeMaxDynamicSharedMemorySize, SMEM_BYTES);

    void *p_ca, *p_cd, *p_rec, *p_wc, *p_wo;
    cudaGetSymbolAddress(&p_ca, g_ca);
    cudaGetSymbolAddress(&p_cd, g_cd);
    cudaGetSymbolAddress(&p_rec, g_rec);
    cudaGetSymbolAddress(&p_wc, g_wc);
    cudaGetSymbolAddress(&p_wo, g_wo);

    void* fn = nullptr;
    cudaDriverEntryPointQueryResult qr;
    cudaGetDriverEntryPoint("cuTensorMapEncodeTiled", &fn, cudaEnableDefault, &qr);
    PFN_encode enc = (PFN_encode)fn;

    CUtensorMap tmAca, tmAcd, tmBa, tmBd, tmArec, tmBo;
    enc2d(enc, &tmAca, p_ca, 1024, (unsigned long long)NB * MP);
    enc2d(enc, &tmAcd, p_cd, 1024, (unsigned long long)NB * MP);
    enc2d(enc, &tmBa, p_wc, 3072, 1024);
    enc2d(enc, &tmBd, (char*)p_wc + (size_t)HH * 3072 * 2, 3072, 1024);
    enc2d(enc, &tmArec, p_rec, 1024, (unsigned long long)NB * SS);
    enc2d(enc, &tmBo, p_wo, 1024, 1024);

    // fused weight prep: 8192 blocks conv + 4096 blocks out
    prep_weights<<<12288, 256>>>(w_approx, w_detail, w_out);
    // fused DWT + zero-pad
    dwt_kernel<<<NB * MM + 16, 256>>>(x);

    // conv GEMMs: M=8192, N=1024, K=3072, both halves in one launch
    conv_gemm<<<dim3(8, 64, 2), 256, SMEM_BYTES>>>(tmAca, tmAcd, tmBa, tmBd,
                                                   b_approx, b_detail);

    // paired iDWT: one block per (b, t) writes rows 2t, 2t+1
    idwt_kernel<<<NB * MM, 256>>>();

    // out GEMM: M=16384, N=1024, K=1024
    out_gemm<<<dim3(8, 128), 256, SMEM_BYTES>>>(tmArec, tmBo, b_out, out);
}